// round 5
// baseline (speedup 1.0000x reference)
#include <cuda_runtime.h>
#include <math.h>

// ---------------------------------------------------------------------------
// Problem constants
// ---------------------------------------------------------------------------
#define T_LEN 512
#define B_SZ  64
#define HID   512
#define G4    2048          // 4*HID (gate rows)
#define CTXD  792
#define INDIM 1048
#define NCTA  256           // persistent recurrence CTAs (2 units each, 2/SM)

typedef unsigned long long ull;

// packed fp32x2 helpers (sm_103a: FFMA2 only reachable via PTX fma.rn.f32x2)
#define FMA2(d,a,b)  asm("fma.rn.f32x2 %0, %1, %2, %0;" : "+l"(d) : "l"(a), "l"(b))
#define ADD2(d,a,b)  asm("add.rn.f32x2 %0, %1, %2;" : "=l"(d) : "l"(a), "l"(b))
#define PK2(d,x,y)   asm("mov.b64 %0, {%1, %2};" : "=l"(d) : "r"(__float_as_uint(x)), "r"(__float_as_uint(y)))
#define UPK2(x,y,d)  do { unsigned _lo,_hi; asm("mov.b64 {%0, %1}, %2;" : "=r"(_lo), "=r"(_hi) : "l"(d)); \
                          (x)=__uint_as_float(_lo); (y)=__uint_as_float(_hi); } while(0)

// ---------------------------------------------------------------------------
// Device scratch
// ---------------------------------------------------------------------------
__device__ float d_gctx[B_SZ * G4];                               // [b][g]
__device__ float d_P[260 * 8 * G4];                               // [(v*8+j)][g]
__device__ float d_gx0[(size_t)T_LEN * B_SZ * G4];                // [t][b][g]
__device__ float d_gx1[(size_t)T_LEN * B_SZ * G4];                // [t][b][g]
__device__ float d_h1T[(size_t)(T_LEN + 1) * HID * B_SZ];         // [t+1][k][b]
__device__ float d_h2T[(size_t)(T_LEN + 1) * HID * B_SZ];         // [t+1][k][b]

__device__ unsigned g_cnt = 0;
__device__ volatile unsigned g_gen = 0;

// ---------------------------------------------------------------------------
// Software grid barrier (all NCTA CTAs co-resident: 2 per SM, 256 <= 2*148)
// ---------------------------------------------------------------------------
__device__ __forceinline__ void grid_sync() {
    __syncthreads();
    if (threadIdx.x == 0) {
        __threadfence();
        unsigned my = g_gen;                     // read BEFORE arriving
        if (atomicAdd(&g_cnt, 1u) == NCTA - 1) {
            g_cnt = 0;
            __threadfence();
            g_gen = my + 1;                      // release
        } else {
            while (g_gen == my) { }              // volatile spin (L2)
        }
    }
    __syncthreads();
}

// ---------------------------------------------------------------------------
// K0: zero the t=0 slabs of both hidden-state buffers.
// ---------------------------------------------------------------------------
__global__ void zero_h0_kernel() {
    int i = blockIdx.x * blockDim.x + threadIdx.x;
    if (i < HID * B_SZ) { d_h1T[i] = 0.f; d_h2T[i] = 0.f; }
}

// ---------------------------------------------------------------------------
// K1: gctx[b][g] = (b_ih0+b_hh0)[g] + ctxvec[b] . W_ih0[g][0:792]
// ---------------------------------------------------------------------------
__global__ __launch_bounds__(256) void gctx_kernel(
    const float* __restrict__ conv,      // [64][512]
    const int*   __restrict__ cat,       // [64][3]
    const float* __restrict__ num,       // [64][16]
    const float* __restrict__ ce0,       // [10][50]
    const float* __restrict__ ce1,       // [128][64]
    const float* __restrict__ ce2,       // [300][150]
    const float* __restrict__ W_ih0,     // [2048][1048]
    const float* __restrict__ b_ih0,
    const float* __restrict__ b_hh0)
{
    __shared__ __align__(16) float ctx[CTXD];
    int b = blockIdx.x, tid = threadIdx.x;
    int i0 = cat[b * 3 + 0], i1 = cat[b * 3 + 1], i2 = cat[b * 3 + 2];
    for (int i = tid; i < 512; i += 256) ctx[i]       = conv[b * 512 + i];
    for (int i = tid; i < 50;  i += 256) ctx[512 + i] = ce0[i0 * 50 + i];
    for (int i = tid; i < 64;  i += 256) ctx[562 + i] = ce1[i1 * 64 + i];
    for (int i = tid; i < 150; i += 256) ctx[626 + i] = ce2[i2 * 150 + i];
    for (int i = tid; i < 16;  i += 256) ctx[776 + i] = num[b * 16 + i];
    __syncthreads();

    const float4* cv = (const float4*)ctx;           // 198 float4s
    for (int g = tid; g < G4; g += 256) {
        const float4* wr = (const float4*)(W_ih0 + (size_t)g * INDIM);
        float acc = b_ih0[g] + b_hh0[g];
        #pragma unroll 4
        for (int kk = 0; kk < 198; ++kk) {
            float4 w = wr[kk], c4 = cv[kk];
            acc = fmaf(w.x, c4.x, fmaf(w.y, c4.y, fmaf(w.z, c4.z, fmaf(w.w, c4.w, acc))));
        }
        d_gctx[b * G4 + g] = acc;
    }
}

// ---------------------------------------------------------------------------
// K2: byte projection table P[(v*8+j)][g] = byte_emb[v] . W_ih0[g][792+32j : +32]
// ---------------------------------------------------------------------------
__global__ __launch_bounds__(256) void ptable_kernel(
    const float* __restrict__ byte_emb,  // [260][32]
    const float* __restrict__ W_ih0)
{
    int pid = blockIdx.x;                // v*8 + j
    int v = pid >> 3, j = pid & 7;
    __shared__ float e[32];
    if (threadIdx.x < 32) e[threadIdx.x] = byte_emb[v * 32 + threadIdx.x];
    __syncthreads();
    for (int g = threadIdx.x; g < G4; g += 256) {
        const float* wr = W_ih0 + (size_t)g * INDIM + CTXD + j * 32;
        float acc = 0.f;
        #pragma unroll
        for (int d = 0; d < 32; ++d) acc = fmaf(e[d], wr[d], acc);
        d_P[(size_t)pid * G4 + g] = acc;
    }
}

// ---------------------------------------------------------------------------
// K3: gx0[t][b][g] = gctx[b][g] + sum_j P[pad(b,t+j)*8+j][g]
// ---------------------------------------------------------------------------
__global__ __launch_bounds__(128) void gx0_kernel(
    const int* __restrict__ payload)     // [64][512]
{
    int t = blockIdx.x, b = blockIdx.y, tid = threadIdx.x;
    __shared__ int rows[8];
    if (tid < 8) {
        int q = t + tid;
        int v = (q < 7) ? 256 : ((q == 7) ? 257 : payload[b * 512 + (q - 8)]);
        rows[tid] = v * 8 + tid;
    }
    __syncthreads();
    float4* outp = (float4*)(d_gx0 + ((size_t)t * B_SZ + b) * G4);
    const float4* gc = (const float4*)(d_gctx + b * G4);
    #pragma unroll
    for (int p = 0; p < 4; ++p) {
        int g4 = p * 128 + tid;          // float4 index, 0..511
        float4 acc = gc[g4];
        #pragma unroll
        for (int j = 0; j < 8; ++j) {
            float4 pv = ((const float4*)(d_P + (size_t)rows[j] * G4))[g4];
            acc.x += pv.x; acc.y += pv.y; acc.z += pv.z; acc.w += pv.w;
        }
        outp[g4] = acc;
    }
}

// ---------------------------------------------------------------------------
// K4/K6: persistent LSTM recurrence with packed f32x2 FMA.
// 256 CTAs x 256 threads (2/SM). CTA owns 2 hidden units.
// Thread (p = tid&31 -> batch pair (2p,2p+1), rg = (tid>>5)&1 -> unit,
// ks = tid>>6 -> K-quarter of 128 k). Per k: 1 LDG.64 (h pair, coalesced) +
// 2 broadcast LDS.128 (pre-splatted (w,w) gate weights) + 4 FFMA2.
// K-split partials combined through smem; ks==0 does pointwise for 2 batches.
// ---------------------------------------------------------------------------
__global__ __launch_bounds__(256, 2) void rec_kernel(
    const float* __restrict__ Whh,       // [2048][512]
    int layer)
{
    const float* gx = layer ? d_gx1 : d_gx0;
    float*       hT = layer ? d_h2T : d_h1T;

    __shared__ __align__(16) float2 Ws[HID][2][4];   // [k][unit][gate] = (w,w)  32 KB
    __shared__ __align__(16) ull Red[2][4][32][4];   // [unit][ks][pair][gate]    8 KB

    int tid = threadIdx.x;
    int u0 = blockIdx.x * 2;
    for (int idx = tid; idx < 8 * HID; idx += 256) {
        int k = idx & 511, r = idx >> 9;             // r = rg*4 + gate
        int gate = r & 3, rg_ = r >> 2;
        float w = Whh[((size_t)gate * HID + u0 + rg_) * HID + k];
        Ws[k][rg_][gate] = make_float2(w, w);
    }
    // (first grid_sync's __syncthreads orders Ws before use)

    int p  = tid & 31;
    int rg = (tid >> 5) & 1;
    int ks = tid >> 6;
    int unit = u0 + rg;
    int kbase = ks * 128;

    // &Ws[k][rg][0] as ulonglong2*: index = k*4 + rg*2 (+0: gates i,f ; +1: g,o)
    const ulonglong2* wp = (const ulonglong2*)Ws + rg * 2;
    ull cc = 0;                                      // cell state pair (c_b0, c_b1)

    for (int t = 0; t < T_LEN; ++t) {
        grid_sync();                                 // h[t] fully published
        const ull* hp = (const ull*)(hT + (size_t)t * (HID * B_SZ) + (size_t)kbase * 64) + p;

        // prefetch gate inputs (consumed only at loop end)
        float q[8];
        if (ks == 0) {
            const float* g0 = gx + ((size_t)t * B_SZ + 2 * p) * G4 + unit;
            #pragma unroll
            for (int g = 0; g < 4; ++g) { q[g] = g0[g * 512]; q[4 + g] = g0[G4 + g * 512]; }
        }

        ull aI = 0, aF = 0, aG = 0, aO = 0;
        #pragma unroll 4
        for (int k = 0; k < 128; ++k) {
            ulonglong2 wIF = wp[(kbase + k) * 4];
            ulonglong2 wGO = wp[(kbase + k) * 4 + 1];
            ull h2 = hp[k * 32];
            FMA2(aI, h2, wIF.x); FMA2(aF, h2, wIF.y);
            FMA2(aG, h2, wGO.x); FMA2(aO, h2, wGO.y);
        }

        if (ks != 0) {
            Red[rg][ks][p][0] = aI; Red[rg][ks][p][1] = aF;
            Red[rg][ks][p][2] = aG; Red[rg][ks][p][3] = aO;
        }
        __syncthreads();
        if (ks == 0) {
            #pragma unroll
            for (int s = 1; s < 4; ++s) {
                ADD2(aI, aI, Red[rg][s][p][0]); ADD2(aF, aF, Red[rg][s][p][1]);
                ADD2(aG, aG, Red[rg][s][p][2]); ADD2(aO, aO, Red[rg][s][p][3]);
            }
            float i0,i1,f0,f1,gg0,gg1,o0,o1,c0,c1;
            UPK2(i0, i1, aI); UPK2(f0, f1, aF);
            UPK2(gg0, gg1, aG); UPK2(o0, o1, aO);
            UPK2(c0, c1, cc);
            i0 += q[0]; f0 += q[1]; gg0 += q[2]; o0 += q[3];
            i1 += q[4]; f1 += q[5]; gg1 += q[6]; o1 += q[7];
            float si0 = 1.f / (1.f + __expf(-i0));
            float sf0 = 1.f / (1.f + __expf(-f0));
            float so0 = 1.f / (1.f + __expf(-o0));
            float si1 = 1.f / (1.f + __expf(-i1));
            float sf1 = 1.f / (1.f + __expf(-f1));
            float so1 = 1.f / (1.f + __expf(-o1));
            c0 = fmaf(sf0, c0, si0 * tanhf(gg0));
            c1 = fmaf(sf1, c1, si1 * tanhf(gg1));
            PK2(cc, c0, c1);
            float h0 = so0 * tanhf(c0), h1 = so1 * tanhf(c1);
            ull hpair; PK2(hpair, h0, h1);
            *((ull*)(hT + (size_t)(t + 1) * (HID * B_SZ) + (size_t)unit * 64) + p) = hpair;
        }
    }
}

// ---------------------------------------------------------------------------
// K5: gx1[t][b][n] = h1[t][:][b] . W_ih1[n][:] + (b_ih1+b_hh1)[n]
// Tiled fp32 GEMM with FFMA2: acc pairs along n come straight from Bs LDS.128;
// a-splats are alu-pipe mov.b64 packs (overlap fma pipe).
// ---------------------------------------------------------------------------
__global__ __launch_bounds__(256) void gemm_gx1_kernel(
    const float* __restrict__ W,         // W_ih1 [2048][512]
    const float* __restrict__ bi,
    const float* __restrict__ bh)
{
    int n0 = blockIdx.x * 64;
    int t  = blockIdx.y;
    __shared__ __align__(16) float As[16][64];
    __shared__ __align__(16) float Bs[16][68];
    int tid = threadIdx.x;
    int tx = tid & 15, ty = tid >> 4;                // tx->n (coalesced writes)
    int lb = tid & 63, lk = tid >> 6;
    int bk = tid & 15, bn = tid >> 4;
    const float* Ap = d_h1T + (size_t)(t + 1) * (HID * B_SZ);
    ull acc[4][2] = {};

    for (int kc = 0; kc < HID; kc += 16) {
        #pragma unroll
        for (int i = 0; i < 4; ++i)
            As[lk + 4 * i][lb] = Ap[(size_t)(kc + lk + 4 * i) * 64 + lb];
        #pragma unroll
        for (int i = 0; i < 4; ++i)
            Bs[bk][bn + 16 * i] = W[(size_t)(n0 + bn + 16 * i) * HID + kc + bk];
        __syncthreads();
        #pragma unroll
        for (int ku = 0; ku < 16; ++ku) {
            float4 av = *(const float4*)&As[ku][ty * 4];
            ulonglong2 bq = *(const ulonglong2*)&Bs[ku][tx * 4];
            ull a0, a1, a2, a3;
            PK2(a0, av.x, av.x); PK2(a1, av.y, av.y);
            PK2(a2, av.z, av.z); PK2(a3, av.w, av.w);
            FMA2(acc[0][0], a0, bq.x); FMA2(acc[0][1], a0, bq.y);
            FMA2(acc[1][0], a1, bq.x); FMA2(acc[1][1], a1, bq.y);
            FMA2(acc[2][0], a2, bq.x); FMA2(acc[2][1], a2, bq.y);
            FMA2(acc[3][0], a3, bq.x); FMA2(acc[3][1], a3, bq.y);
        }
        __syncthreads();
    }
    ull bz01, bz23;
    {
        float z0 = bi[n0 + tx * 4 + 0] + bh[n0 + tx * 4 + 0];
        float z1 = bi[n0 + tx * 4 + 1] + bh[n0 + tx * 4 + 1];
        float z2 = bi[n0 + tx * 4 + 2] + bh[n0 + tx * 4 + 2];
        float z3 = bi[n0 + tx * 4 + 3] + bh[n0 + tx * 4 + 3];
        PK2(bz01, z0, z1); PK2(bz23, z2, z3);
    }
    #pragma unroll
    for (int i = 0; i < 4; ++i) {
        int b = ty * 4 + i;
        union { ull u[2]; float4 f; } st;
        ADD2(st.u[0], acc[i][0], bz01);
        ADD2(st.u[1], acc[i][1], bz23);
        *(float4*)(d_gx1 + ((size_t)t * B_SZ + b) * G4 + n0 + tx * 4) = st.f;
    }
}

// ---------------------------------------------------------------------------
// K7: logits[b][t][v] = h2[t][:][b] . W_out[v][:] + b_out[v]  (FFMA2 tiling)
// ---------------------------------------------------------------------------
__global__ __launch_bounds__(256) void logits_kernel(
    const float* __restrict__ W,         // W_out [256][512]
    const float* __restrict__ bo,
    float* __restrict__ out)             // [64][512][256]
{
    int n0 = blockIdx.x * 64;
    int t  = blockIdx.y;
    __shared__ __align__(16) float As[16][64];
    __shared__ __align__(16) float Bs[16][68];
    int tid = threadIdx.x;
    int tx = tid & 15, ty = tid >> 4;
    int lb = tid & 63, lk = tid >> 6;
    int bk = tid & 15, bn = tid >> 4;
    const float* Ap = d_h2T + (size_t)(t + 1) * (HID * B_SZ);
    ull acc[4][2] = {};

    for (int kc = 0; kc < HID; kc += 16) {
        #pragma unroll
        for (int i = 0; i < 4; ++i)
            As[lk + 4 * i][lb] = Ap[(size_t)(kc + lk + 4 * i) * 64 + lb];
        #pragma unroll
        for (int i = 0; i < 4; ++i)
            Bs[bk][bn + 16 * i] = W[(size_t)(n0 + bn + 16 * i) * HID + kc + bk];
        __syncthreads();
        #pragma unroll
        for (int ku = 0; ku < 16; ++ku) {
            float4 av = *(const float4*)&As[ku][ty * 4];
            ulonglong2 bq = *(const ulonglong2*)&Bs[ku][tx * 4];
            ull a0, a1, a2, a3;
            PK2(a0, av.x, av.x); PK2(a1, av.y, av.y);
            PK2(a2, av.z, av.z); PK2(a3, av.w, av.w);
            FMA2(acc[0][0], a0, bq.x); FMA2(acc[0][1], a0, bq.y);
            FMA2(acc[1][0], a1, bq.x); FMA2(acc[1][1], a1, bq.y);
            FMA2(acc[2][0], a2, bq.x); FMA2(acc[2][1], a2, bq.y);
            FMA2(acc[3][0], a3, bq.x); FMA2(acc[3][1], a3, bq.y);
        }
        __syncthreads();
    }
    ull bz01, bz23;
    {
        float z0 = bo[n0 + tx * 4 + 0];
        float z1 = bo[n0 + tx * 4 + 1];
        float z2 = bo[n0 + tx * 4 + 2];
        float z3 = bo[n0 + tx * 4 + 3];
        PK2(bz01, z0, z1); PK2(bz23, z2, z3);
    }
    #pragma unroll
    for (int i = 0; i < 4; ++i) {
        int b = ty * 4 + i;
        union { ull u[2]; float4 f; } st;
        ADD2(st.u[0], acc[i][0], bz01);
        ADD2(st.u[1], acc[i][1], bz23);
        *(float4*)(out + ((size_t)b * T_LEN + t) * 256 + n0 + tx * 4) = st.f;
    }
}

// ---------------------------------------------------------------------------
// kernel_launch
// ---------------------------------------------------------------------------
extern "C" void kernel_launch(void* const* d_in, const int* in_sizes, int n_in,
                              void* d_out, int out_size) {
    const float* ecc     = (const float*)d_in[0];   // [64,512]
    const int*   cat     = (const int*)  d_in[1];   // [64,3]
    const float* num     = (const float*)d_in[2];   // [64,16]
    const int*   payload = (const int*)  d_in[3];   // [64,512]
    const float* ce0     = (const float*)d_in[4];
    const float* ce1     = (const float*)d_in[5];
    const float* ce2     = (const float*)d_in[6];
    const float* bemb    = (const float*)d_in[7];
    const float* W_ih0   = (const float*)d_in[8];
    const float* W_hh0   = (const float*)d_in[9];
    const float* b_ih0   = (const float*)d_in[10];
    const float* b_hh0   = (const float*)d_in[11];
    const float* W_ih1   = (const float*)d_in[12];
    const float* W_hh1   = (const float*)d_in[13];
    const float* b_ih1   = (const float*)d_in[14];
    const float* b_hh1   = (const float*)d_in[15];
    const float* W_outp  = (const float*)d_in[16];
    const float* b_outp  = (const float*)d_in[17];
    float* out = (float*)d_out;

    zero_h0_kernel<<<64, 512>>>();
    gctx_kernel<<<64, 256>>>(ecc, cat, num, ce0, ce1, ce2, W_ih0, b_ih0, b_hh0);
    ptable_kernel<<<2080, 256>>>(bemb, W_ih0);
    gx0_kernel<<<dim3(T_LEN, B_SZ), 128>>>(payload);
    rec_kernel<<<NCTA, 256>>>(W_hh0, 0);
    gemm_gx1_kernel<<<dim3(32, T_LEN), 256>>>(W_ih1, b_ih1, b_hh1);
    rec_kernel<<<NCTA, 256>>>(W_hh1, 1);
    logits_kernel<<<dim3(4, T_LEN), 256>>>(W_outp, b_outp, out);
}